// round 1
// baseline (speedup 1.0000x reference)
#include <cuda_runtime.h>
#include <cuda_bf16.h>
#include <math.h>

// Problem constants
#define BB   8
#define LL   2048
#define DD   768
#define ORD  128
#define NFFT 4096
#define MM   (BB*LL)          // 16384
#define N3D  (3*DD)           // 2304

#define MIN_DECAY (-3.0701134573253945f)
#define MAX_DECAY (-15.350567286626972f)

// ---------------- scratch (device globals; no allocations allowed) ------------
__device__ float  g_k[DD * LL];            // filter k[d][l]
__device__ float2 g_Kf[DD * NFFT];         // FFT(k) in DIF (bit-reversed) order
__device__ float  g_xbuf[(size_t)MM * N3D];// u @ in_W + b   [m][c]
__device__ float  g_vg [BB * DD * LL];     // conv(v)*conv(x1), channel-major
__device__ float  g_x2g[BB * DD * LL];     // conv(x2), channel-major
__device__ float  g_ybT[BB * DD * LL];     // gated fftconv output, channel-major

__device__ __forceinline__ float2 cmul(float2 a, float2 b) {
    return make_float2(a.x*b.x - a.y*b.y, a.x*b.y + a.y*b.x);
}

// =====================================================================
// Kernel 1: Hyena filter  ->  g_k[d][l]
// grid 128 CTAs (16 rows of l each), 128 threads (one per ORDER lane)
// =====================================================================
__global__ __launch_bounds__(128) void filter_kernel(
    const float* __restrict__ z,        // [L,5]
    const float* __restrict__ sin_freq, // [128]
    const float* __restrict__ eo_mat,   // [5,128]
    const float* __restrict__ eo_bias,  // [128]
    const float* __restrict__ oo1,      // [128,128]
    const float* __restrict__ oo1_b,
    const float* __restrict__ oo2,
    const float* __restrict__ oo2_b,
    const float* __restrict__ oh)       // [128,768]
{
    __shared__ float hA[16][129];
    __shared__ float hB[16][129];
    const int o  = threadIdx.x;
    const int l0 = blockIdx.x * 16;
    const float f = sin_freq[o];

    // layer 1: z @ eo
    #pragma unroll 1
    for (int l = 0; l < 16; l++) {
        float acc = eo_bias[o];
        #pragma unroll
        for (int e = 0; e < 5; e++) acc += z[(l0+l)*5 + e] * eo_mat[e*ORD + o];
        hA[l][o] = sinf(f * acc);
    }
    __syncthreads();
    // layer 2
    #pragma unroll 1
    for (int l = 0; l < 16; l++) {
        float acc = oo1_b[o];
        #pragma unroll 4
        for (int p = 0; p < ORD; p++) acc += hA[l][p] * oo1[p*ORD + o];
        hB[l][o] = sinf(f * acc);
    }
    __syncthreads();
    // layer 3
    #pragma unroll 1
    for (int l = 0; l < 16; l++) {
        float acc = oo2_b[o];
        #pragma unroll 4
        for (int p = 0; p < ORD; p++) acc += hB[l][p] * oo2[p*ORD + o];
        hA[l][o] = sinf(f * acc);
    }
    __syncthreads();
    // projection to D + decay envelope
    #pragma unroll 1
    for (int c = 0; c < DD/ORD; c++) {
        const int d = o + c * ORD;
        float acc[16];
        #pragma unroll
        for (int l = 0; l < 16; l++) acc[l] = 0.f;
        #pragma unroll 2
        for (int p = 0; p < ORD; p++) {
            const float w = oh[p*DD + d];
            #pragma unroll
            for (int l = 0; l < 16; l++) acc[l] += hA[l][p] * w;
        }
        const float delta = fabsf(MIN_DECAY + (MAX_DECAY - MIN_DECAY) * ((float)d / 767.0f));
        #pragma unroll
        for (int l = 0; l < 16; l++) {
            const int lg = l0 + l;
            const float t = (float)lg / 2047.0f;
            g_k[d*LL + lg] = acc[l] * expf(-t * delta);
        }
    }
}

// =====================================================================
// FFT helpers: 4096-pt complex, 256 threads, shared data + twiddles
// forward = DIF (natural in -> bit-reversed out)
// inverse = DIT w/ conj twiddles (bit-reversed in -> natural out), unscaled
// =====================================================================
__device__ __forceinline__ void fill_twiddles(float2* tw, int tid) {
    for (int j = tid; j < NFFT/2; j += 256) {
        float s, c;
        sincospif(-(float)j / 2048.0f, &s, &c);  // exp(-i*2*pi*j/4096)
        tw[j] = make_float2(c, s);
    }
}

__device__ void fft_dif_fwd(float2* data, const float2* tw, int tid) {
    #pragma unroll 1
    for (int s = 11; s >= 0; s--) {
        const int span = 1 << s;
        #pragma unroll
        for (int t = 0; t < 8; t++) {
            const int idx  = tid + t * 256;
            const int j    = idx & (span - 1);
            const int base = ((idx >> s) << (s + 1)) + j;
            const float2 a = data[base];
            const float2 b = data[base + span];
            data[base] = make_float2(a.x + b.x, a.y + b.y);
            const float2 d2 = make_float2(a.x - b.x, a.y - b.y);
            data[base + span] = cmul(d2, tw[j << (11 - s)]);
        }
        __syncthreads();
    }
}

__device__ void fft_dit_inv(float2* data, const float2* tw, int tid) {
    #pragma unroll 1
    for (int s = 0; s <= 11; s++) {
        const int span = 1 << s;
        #pragma unroll
        for (int t = 0; t < 8; t++) {
            const int idx  = tid + t * 256;
            const int j    = idx & (span - 1);
            const int base = ((idx >> s) << (s + 1)) + j;
            float2 w = tw[j << (11 - s)];
            w.y = -w.y;                       // conjugate
            const float2 a = data[base];
            const float2 b = cmul(data[base + span], w);
            data[base]        = make_float2(a.x + b.x, a.y + b.y);
            data[base + span] = make_float2(a.x - b.x, a.y - b.y);
        }
        __syncthreads();
    }
}

// =====================================================================
// Kernel 2: FFT of filter k  ->  g_Kf (bit-reversed order)
// =====================================================================
__global__ __launch_bounds__(256) void fftk_kernel() {
    __shared__ float2 data[NFFT];
    __shared__ float2 tw[NFFT/2];
    const int d = blockIdx.x;
    const int tid = threadIdx.x;
    fill_twiddles(tw, tid);
    for (int i = tid; i < LL; i += 256) {
        data[i]      = make_float2(g_k[d*LL + i], 0.f);
        data[i + LL] = make_float2(0.f, 0.f);
    }
    __syncthreads();
    fft_dif_fwd(data, tw, tid);
    for (int i = tid; i < NFFT; i += 256) g_Kf[(size_t)d*NFFT + i] = data[i];
}

// =====================================================================
// Kernel 3: GEMM1  C[m][n] = u[m][:] @ in_W + in_b,  M=16384 N=2304 K=768
// 128x128x16 tile, 256 threads, 8x8 per thread
// =====================================================================
__global__ __launch_bounds__(256) void gemm1_kernel(
    const float* __restrict__ A, const float* __restrict__ B,
    const float* __restrict__ bias, float* __restrict__ C)
{
    const int Mk = 768, Nn = N3D;
    __shared__ __align__(16) float As[16][132];
    __shared__ __align__(16) float Bs[16][128];
    const int tid = threadIdx.x;
    const int m0 = blockIdx.y * 128;
    const int n0 = blockIdx.x * 128;
    const int tx = tid & 15, ty = tid >> 4;
    float acc[8][8];
    #pragma unroll
    for (int i = 0; i < 8; i++)
        #pragma unroll
        for (int j = 0; j < 8; j++) acc[i][j] = 0.f;

    for (int k0 = 0; k0 < Mk; k0 += 16) {
        #pragma unroll
        for (int t = 0; t < 2; t++) {
            const int v = tid + t*256;
            const int row = v >> 2;
            const int cg  = (v & 3) * 4;
            float4 a4 = *reinterpret_cast<const float4*>(&A[(size_t)(m0+row)*Mk + k0 + cg]);
            As[cg+0][row] = a4.x; As[cg+1][row] = a4.y;
            As[cg+2][row] = a4.z; As[cg+3][row] = a4.w;
        }
        #pragma unroll
        for (int t = 0; t < 2; t++) {
            const int v = tid + t*256;
            const int row = v >> 5;
            const int cg  = (v & 31) * 4;
            *reinterpret_cast<float4*>(&Bs[row][cg]) =
                *reinterpret_cast<const float4*>(&B[(size_t)(k0+row)*Nn + n0 + cg]);
        }
        __syncthreads();
        #pragma unroll
        for (int kk = 0; kk < 16; kk++) {
            float a[8], b[8];
            *reinterpret_cast<float4*>(&a[0]) = *reinterpret_cast<const float4*>(&As[kk][ty*8]);
            *reinterpret_cast<float4*>(&a[4]) = *reinterpret_cast<const float4*>(&As[kk][ty*8+4]);
            *reinterpret_cast<float4*>(&b[0]) = *reinterpret_cast<const float4*>(&Bs[kk][tx*8]);
            *reinterpret_cast<float4*>(&b[4]) = *reinterpret_cast<const float4*>(&Bs[kk][tx*8+4]);
            #pragma unroll
            for (int i = 0; i < 8; i++)
                #pragma unroll
                for (int j = 0; j < 8; j++) acc[i][j] += a[i] * b[j];
        }
        __syncthreads();
    }
    #pragma unroll
    for (int i = 0; i < 8; i++) {
        const int m = m0 + ty*8 + i;
        #pragma unroll
        for (int j = 0; j < 8; j += 4) {
            const int n = n0 + tx*8 + j;
            float4 r;
            r.x = acc[i][j+0] + bias[n+0];
            r.y = acc[i][j+1] + bias[n+1];
            r.z = acc[i][j+2] + bias[n+2];
            r.w = acc[i][j+3] + bias[n+3];
            *reinterpret_cast<float4*>(&C[(size_t)m*Nn + n]) = r;
        }
    }
}

// =====================================================================
// Kernel 3b: depthwise conv-4 (causal) + gating + transpose
// grid (d-tiles=24, l-tiles=64, b=8), 256 threads; tile = 32 d x 32 l
// =====================================================================
__global__ __launch_bounds__(256) void convgate_kernel(
    const float* __restrict__ x1_s, const float* __restrict__ x2_s,
    const float* __restrict__ v_s,
    const float* __restrict__ x1_sb, const float* __restrict__ x2_sb,
    const float* __restrict__ v_sb)
{
    __shared__ float sh1[35*33];
    __shared__ float sh2[35*33];
    __shared__ float shv[35*33];
    const int tid = threadIdx.x;
    const int d0 = blockIdx.x * 32;
    const int l0 = blockIdx.y * 32;
    const int b  = blockIdx.z;

    // load three 35x32 halo tiles (rows = l0-3 .. l0+31)
    for (int idx = tid; idx < 35*32; idx += 256) {
        const int r  = idx >> 5;
        const int cc = idx & 31;
        const int lg = l0 - 3 + r;
        float v1 = 0.f, v2 = 0.f, vv = 0.f;
        if (lg >= 0) {
            const size_t rowbase = ((size_t)(b*LL + lg)) * N3D + d0 + cc;
            v1 = g_xbuf[rowbase];
            v2 = g_xbuf[rowbase + DD];
            vv = g_xbuf[rowbase + 2*DD];
        }
        sh1[r*33 + cc] = v1;
        sh2[r*33 + cc] = v2;
        shv[r*33 + cc] = vv;
    }
    __syncthreads();

    #pragma unroll
    for (int t = 0; t < 4; t++) {
        const int o  = tid + t*256;
        const int dd = o >> 5;
        const int ll = o & 31;
        const int d  = d0 + dd;
        float c1 = x1_sb[d], c2 = x2_sb[d], cv = v_sb[d];
        #pragma unroll
        for (int j = 0; j < 4; j++) {
            const int r = ll + j;
            c1 += x1_s[d*4 + j] * sh1[r*33 + dd];
            c2 += x2_s[d*4 + j] * sh2[r*33 + dd];
            cv += v_s [d*4 + j] * shv[r*33 + dd];
        }
        const size_t out = ((size_t)(b*DD + d)) * LL + l0 + ll;
        g_vg [out] = cv * c1;
        g_x2g[out] = c2;
    }
}

// =====================================================================
// Kernel 4: per-channel FFT convolution + D_bias + x2 gate
// grid = B*D CTAs, 256 threads
// =====================================================================
__global__ __launch_bounds__(256) void fftconv_kernel(const float* __restrict__ D_bias) {
    __shared__ float2 data[NFFT];
    __shared__ float2 tw[NFFT/2];
    const int bd  = blockIdx.x;          // b*768 + d
    const int d   = bd % DD;
    const int tid = threadIdx.x;
    const size_t ch = (size_t)bd * LL;

    fill_twiddles(tw, tid);
    float vc[8];
    #pragma unroll
    for (int i = 0; i < 8; i++) {
        const int l = tid + i*256;
        const float v = g_vg[ch + l];
        vc[i] = v;
        data[l]      = make_float2(v, 0.f);
        data[l + LL] = make_float2(0.f, 0.f);
    }
    __syncthreads();

    fft_dif_fwd(data, tw, tid);          // ends with __syncthreads()

    const float2* __restrict__ kf = &g_Kf[(size_t)d * NFFT];
    for (int i = tid; i < NFFT; i += 256) data[i] = cmul(data[i], kf[i]);
    __syncthreads();

    fft_dit_inv(data, tw, tid);          // ends with __syncthreads()

    const float db = D_bias[d];
    #pragma unroll
    for (int i = 0; i < 8; i++) {
        const int l = tid + i*256;
        const float yr = data[l].x * (1.0f / (float)NFFT);
        const float x2 = g_x2g[ch + l];
        g_ybT[ch + l] = (yr + vc[i] * db) * x2;
    }
}

// =====================================================================
// Kernel 5: GEMM2  out[m][n] = ybT^T[m][:] @ out_W + out_b
// A is stored transposed (channel-major), N=768 K=768
// =====================================================================
__global__ __launch_bounds__(256) void gemm2_kernel(
    const float* __restrict__ B, const float* __restrict__ bias,
    float* __restrict__ C)
{
    const int Mk = DD, Nn = DD;
    __shared__ __align__(16) float As[16][132];
    __shared__ __align__(16) float Bs[16][128];
    const int tid = threadIdx.x;
    const int m0 = blockIdx.y * 128;
    const int n0 = blockIdx.x * 128;
    const int b  = m0 / LL;
    const int l0 = m0 % LL;
    const int tx = tid & 15, ty = tid >> 4;
    float acc[8][8];
    #pragma unroll
    for (int i = 0; i < 8; i++)
        #pragma unroll
        for (int j = 0; j < 8; j++) acc[i][j] = 0.f;

    for (int k0 = 0; k0 < Mk; k0 += 16) {
        #pragma unroll
        for (int t = 0; t < 2; t++) {
            const int v = tid + t*256;
            const int row = v >> 5;                 // k within tile
            const int cg  = (v & 31) * 4;           // m within tile
            *reinterpret_cast<float4*>(&As[row][cg]) =
                *reinterpret_cast<const float4*>(&g_ybT[((size_t)(b*DD + k0 + row))*LL + l0 + cg]);
        }
        #pragma unroll
        for (int t = 0; t < 2; t++) {
            const int v = tid + t*256;
            const int row = v >> 5;
            const int cg  = (v & 31) * 4;
            *reinterpret_cast<float4*>(&Bs[row][cg]) =
                *reinterpret_cast<const float4*>(&B[(size_t)(k0+row)*Nn + n0 + cg]);
        }
        __syncthreads();
        #pragma unroll
        for (int kk = 0; kk < 16; kk++) {
            float a[8], bb[8];
            *reinterpret_cast<float4*>(&a[0])  = *reinterpret_cast<const float4*>(&As[kk][ty*8]);
            *reinterpret_cast<float4*>(&a[4])  = *reinterpret_cast<const float4*>(&As[kk][ty*8+4]);
            *reinterpret_cast<float4*>(&bb[0]) = *reinterpret_cast<const float4*>(&Bs[kk][tx*8]);
            *reinterpret_cast<float4*>(&bb[4]) = *reinterpret_cast<const float4*>(&Bs[kk][tx*8+4]);
            #pragma unroll
            for (int i = 0; i < 8; i++)
                #pragma unroll
                for (int j = 0; j < 8; j++) acc[i][j] += a[i] * bb[j];
        }
        __syncthreads();
    }
    #pragma unroll
    for (int i = 0; i < 8; i++) {
        const int m = m0 + ty*8 + i;
        #pragma unroll
        for (int j = 0; j < 8; j += 4) {
            const int n = n0 + tx*8 + j;
            float4 r;
            r.x = acc[i][j+0] + bias[n+0];
            r.y = acc[i][j+1] + bias[n+1];
            r.z = acc[i][j+2] + bias[n+2];
            r.w = acc[i][j+3] + bias[n+3];
            *reinterpret_cast<float4*>(&C[(size_t)m*Nn + n]) = r;
        }
    }
}

// =====================================================================
// launch
// =====================================================================
extern "C" void kernel_launch(void* const* d_in, const int* in_sizes, int n_in,
                              void* d_out, int out_size) {
    const float* u      = (const float*)d_in[0];
    const float* in_W   = (const float*)d_in[1];
    const float* in_b   = (const float*)d_in[2];
    const float* out_W  = (const float*)d_in[3];
    const float* out_b  = (const float*)d_in[4];
    const float* x1_s   = (const float*)d_in[5];
    const float* x2_s   = (const float*)d_in[6];
    const float* v_s    = (const float*)d_in[7];
    const float* x1_sb  = (const float*)d_in[8];
    const float* x2_sb  = (const float*)d_in[9];
    const float* v_sb   = (const float*)d_in[10];
    const float* D_bias = (const float*)d_in[11];
    const float* z      = (const float*)d_in[12];
    const float* sfreq  = (const float*)d_in[13];
    const float* eo_mat = (const float*)d_in[14];
    const float* eo_b   = (const float*)d_in[15];
    const float* oo1    = (const float*)d_in[16];
    const float* oo1_b  = (const float*)d_in[17];
    const float* oo2    = (const float*)d_in[18];
    const float* oo2_b  = (const float*)d_in[19];
    const float* oh     = (const float*)d_in[20];
    float* out = (float*)d_out;

    filter_kernel<<<LL/16, 128>>>(z, sfreq, eo_mat, eo_b, oo1, oo1_b, oo2, oo2_b, oh);
    fftk_kernel<<<DD, 256>>>();

    float* xbuf;
    cudaGetSymbolAddress((void**)&xbuf, g_xbuf);
    gemm1_kernel<<<dim3(N3D/128, MM/128), 256>>>(u, in_W, in_b, xbuf);

    convgate_kernel<<<dim3(DD/32, LL/32, BB), 256>>>(x1_s, x2_s, v_s, x1_sb, x2_sb, v_sb);
    fftconv_kernel<<<BB*DD, 256>>>(D_bias);
    gemm2_kernel<<<dim3(DD/128, MM/128), 256>>>(out_W, out_b, out);
}